// round 15
// baseline (speedup 1.0000x reference)
#include <cuda_runtime.h>
#include <cuda_fp16.h>
#include <math.h>
#include <stdint.h>

// Fixed problem shape: B=2048, S=1, E=1024, H=128, DK=NW=8.
#define M_DIM 2048
#define E_DIM 1024

#define BM 128
#define BN 128
#define BK 32
#define NKIT (E_DIM / BK)      // 32
#define STAGES 3
#define STAGE_BYTES 16384      // A(8K) B(8K)
#define SMEM_TOTAL (STAGES * STAGE_BYTES)   // 49152

// -------- device scratch (no cudaMalloc allowed) --------
__device__ __half g_xh[M_DIM * E_DIM];    // x fp16
__device__ __half g_wvh[E_DIM * E_DIM];   // wv fp16
__device__ __half g_qh[M_DIM * E_DIM];    // q fp16
__device__ __half g_wch[E_DIM * E_DIM];   // wc fp16

// -------- helpers --------
struct alignas(16) hf8 { __half h[8]; };

#define CP_ASYNC16(dst, src) \
    asm volatile("cp.async.cg.shared.global [%0], [%1], 16;\n" :: "r"(dst), "l"(src))

#define LDSM4(r, addr) \
    asm volatile("ldmatrix.sync.aligned.m8n8.x4.shared.b16 {%0,%1,%2,%3}, [%4];" \
        : "=r"((r)[0]), "=r"((r)[1]), "=r"((r)[2]), "=r"((r)[3]) : "r"(addr))

__device__ __forceinline__ void mma_f16(float* d, const uint32_t* a, const uint32_t* b) {
    asm volatile(
        "mma.sync.aligned.m16n8k16.row.col.f32.f16.f16.f32 "
        "{%0,%1,%2,%3}, {%4,%5,%6,%7}, {%8,%9}, {%0,%1,%2,%3};\n"
        : "+f"(d[0]), "+f"(d[1]), "+f"(d[2]), "+f"(d[3])
        : "r"(a[0]), "r"(a[1]), "r"(a[2]), "r"(a[3]), "r"(b[0]), "r"(b[1]));
}

__device__ __forceinline__ hf8 cvt8(float4 a, float4 b) {
    hf8 o;
    o.h[0] = __float2half_rn(a.x); o.h[1] = __float2half_rn(a.y);
    o.h[2] = __float2half_rn(a.z); o.h[3] = __float2half_rn(a.w);
    o.h[4] = __float2half_rn(b.x); o.h[5] = __float2half_rn(b.y);
    o.h[6] = __float2half_rn(b.z); o.h[7] = __float2half_rn(b.w);
    return o;
}

// -------- merged prologue: convert x, wv, wc to fp16 (proven ~7us floor) ----
#define CONV_T (E_DIM * E_DIM / 8)     // 131072 threads = 512 blocks x 256

__global__ void conv_all(const float* __restrict__ x,  __half* __restrict__ xh,
                         const float* __restrict__ wv, __half* __restrict__ wvh,
                         const float* __restrict__ wc, __half* __restrict__ wch)
{
    const int t = blockIdx.x * blockDim.x + threadIdx.x;
    const float4* xs  = reinterpret_cast<const float4*>(x);
    const float4* wvs = reinterpret_cast<const float4*>(wv);
    const float4* wcs = reinterpret_cast<const float4*>(wc);

    float4 v0 = xs[2 * t];
    float4 v1 = xs[2 * t + 1];
    float4 v2 = xs[2 * (t + CONV_T)];
    float4 v3 = xs[2 * (t + CONV_T) + 1];
    float4 v4 = wvs[2 * t];
    float4 v5 = wvs[2 * t + 1];
    float4 v6 = wcs[2 * t];
    float4 v7 = wcs[2 * t + 1];

    reinterpret_cast<hf8*>(xh)[t]           = cvt8(v0, v1);
    reinterpret_cast<hf8*>(xh)[t + CONV_T]  = cvt8(v2, v3);
    reinterpret_cast<hf8*>(wvh)[t]          = cvt8(v4, v5);
    reinterpret_cast<hf8*>(wch)[t]          = cvt8(v6, v7);
}

// -------- GEMM: C[M,N] = A[M,K] @ B[N,K]^T, single-term fp16 --------
// 128 threads, 4 warps (2x2), warp tile 64x64 -> 16 LDSM : 64 HMMA per iter
// (4:1 density, matching the measured 12.8 cyc/HMMA regime).
// 3-stage cp.async pipeline (BK=32), one __syncthreads per K-iter.
// FUSE_Q: epilogue applies closed-form quantum layer -> fp16 Qh
template <bool FUSE_Q>
__global__ void __launch_bounds__(128, 1)
gemm_k(const __half* __restrict__ Ah, const __half* __restrict__ Bh,
       const float* __restrict__ bias, float* __restrict__ C,
       __half* __restrict__ Qh, const float* __restrict__ rx)
{
    extern __shared__ char smem[];
    const uint32_t sbase = (uint32_t)__cvta_generic_to_shared(smem);

    const int tid  = threadIdx.x;
    const int lane = tid & 31;
    const int warp = tid >> 5;         // 0..3
    const int bm0 = blockIdx.y * BM;
    const int bn0 = blockIdx.x * BN;
    const int wm = (warp & 1) * 64;    // 2 warps along M, warp tile 64
    const int wn = (warp >> 1) * 64;   // 2 warps along N, warp tile 64
    const int gp = lane >> 2, tg = lane & 3;

    // ---- preload per-thread epilogue constants ----
    float bias_r[16];
    float rxe = 0.0f, rxo = 0.0f;
    if (FUSE_Q) {
        rxe = rx[tg * 2];
        rxo = rx[tg * 2 + 1];
    } else {
#pragma unroll
        for (int nt = 0; nt < 8; nt++) {
            const int n = bn0 + wn + nt * 8 + tg * 2;
            bias_r[2 * nt]     = bias[n];
            bias_r[2 * nt + 1] = bias[n + 1];
        }
    }

    // ---- cp.async: 128 threads cover 64 rows x 2 chunk-pairs, 2 row-halves ----
    const int r0 = tid >> 1;           // 0..63
    const int c0 = (tid & 1) * 2;      // first of 2 chunks
    uint32_t sdj[2];
    size_t gAj[2], gBj[2];
#pragma unroll
    for (int j = 0; j < 2; j++) {
        const int cj = c0 + j;
        sdj[j] = (uint32_t)r0 * 64 + (uint32_t)((cj ^ ((r0 >> 1) & 3)) * 16);
        gAj[j] = (size_t)(bm0 + r0) * E_DIM + cj * 8;
        gBj[j] = (size_t)(bn0 + r0) * E_DIM + cj * 8;
    }

    auto load_stage = [&](int s, int kt) {
        uint32_t base = sbase + (uint32_t)s * STAGE_BYTES;
#pragma unroll
        for (int j = 0; j < 2; j++) {
            CP_ASYNC16(base + sdj[j],               Ah + gAj[j] + kt);
            CP_ASYNC16(base + sdj[j] + 4096,        Ah + gAj[j] + 64 * E_DIM + kt);
            CP_ASYNC16(base + 8192 + sdj[j],        Bh + gBj[j] + kt);
            CP_ASYNC16(base + 8192 + sdj[j] + 4096, Bh + gBj[j] + 64 * E_DIM + kt);
        }
        asm volatile("cp.async.commit_group;\n");
    };

    // ---- ldmatrix per-thread addresses (stage 0, ks 0) ----
    const int arow = ((lane >> 3) & 1) * 8 + (lane & 7);
    const int achk = (lane >> 4) & 1;
    uint32_t addrA[4];   // [mt]
#pragma unroll
    for (int mt = 0; mt < 4; mt++) {
        int rA = wm + mt * 16 + arow;
        addrA[mt] = sbase + (uint32_t)rA * 64 +
                    (uint32_t)((achk ^ ((rA >> 1) & 3)) * 16);
    }
    const int brow = ((lane >> 4) & 1) * 8 + (lane & 7);
    const int bchk = (lane >> 3) & 1;
    uint32_t addrB[4];   // [pair] — 4 pairs cover 64 N
#pragma unroll
    for (int p = 0; p < 4; p++) {
        int rB = wn + p * 16 + brow;
        addrB[p] = sbase + 8192u + (uint32_t)rB * 64 +
                   (uint32_t)((bchk ^ ((rB >> 1) & 3)) * 16);
    }

    float acc[4][8][4];
#pragma unroll
    for (int mt = 0; mt < 4; mt++)
#pragma unroll
        for (int nt = 0; nt < 8; nt++)
#pragma unroll
            for (int i = 0; i < 4; i++) acc[mt][nt][i] = 0.0f;

    load_stage(0, 0);
    load_stage(1, BK);

    for (int it = 0; it < NKIT; it++) {
        if (it < NKIT - 1) asm volatile("cp.async.wait_group 1;\n");
        else               asm volatile("cp.async.wait_group 0;\n");
        __syncthreads();
        if (it + 2 < NKIT) load_stage((it + 2) % STAGES, (it + 2) * BK);

        const uint32_t so = (uint32_t)(it % STAGES) * STAGE_BYTES;

        // prefetch ALL fragments for both ks, then issue 64 dense HMMAs
        uint32_t a0[4][4], a1[4][4], b0[4][4], b1[4][4];
#pragma unroll
        for (int mt = 0; mt < 4; mt++) {
            LDSM4(a0[mt], (addrA[mt] + so));
            LDSM4(a1[mt], (addrA[mt] + so) ^ 32u);
        }
#pragma unroll
        for (int p = 0; p < 4; p++) {
            LDSM4(b0[p], (addrB[p] + so));
            LDSM4(b1[p], (addrB[p] + so) ^ 32u);
        }
#pragma unroll
        for (int mt = 0; mt < 4; mt++)
#pragma unroll
            for (int p = 0; p < 4; p++) {
                mma_f16(acc[mt][2 * p],     a0[mt], &b0[p][0]);
                mma_f16(acc[mt][2 * p + 1], a0[mt], &b0[p][2]);
            }
#pragma unroll
        for (int mt = 0; mt < 4; mt++)
#pragma unroll
            for (int p = 0; p < 4; p++) {
                mma_f16(acc[mt][2 * p],     a1[mt], &b1[p][0]);
                mma_f16(acc[mt][2 * p + 1], a1[mt], &b1[p][2]);
            }
    }

    // ---- epilogue ----
    if (!FUSE_Q) {
#pragma unroll
        for (int nt = 0; nt < 8; nt++) {
            const int n = bn0 + wn + nt * 8 + tg * 2;
            const float b0v = bias_r[2 * nt], b1v = bias_r[2 * nt + 1];
#pragma unroll
            for (int mt = 0; mt < 4; mt++) {
                const int m = bm0 + wm + mt * 16 + gp;
                float2 o0 = make_float2(acc[mt][nt][0] + b0v, acc[mt][nt][1] + b1v);
                float2 o1 = make_float2(acc[mt][nt][2] + b0v, acc[mt][nt][3] + b1v);
                *reinterpret_cast<float2*>(C + (size_t)m * E_DIM + n) = o0;
                *reinterpret_cast<float2*>(C + (size_t)(m + 8) * E_DIM + n) = o1;
            }
        }
    } else {
        // Quantum closed form across each quad (lanes tg=0..3 share one 8-wire
        // head; thread tg owns wires 2tg, 2tg+1). Emit fp16.
        //   c_j = cos(v_j + rx_j);  q[w] = c0..cw (w>=1);  q[0] = c1..c7
#pragma unroll
        for (int nt = 0; nt < 8; nt++) {
            const int n = bn0 + wn + nt * 8 + tg * 2;
#pragma unroll
            for (int mt = 0; mt < 4; mt++) {
#pragma unroll
                for (int h2 = 0; h2 < 2; h2++) {
                    const float va = acc[mt][nt][2 * h2];
                    const float vb = acc[mt][nt][2 * h2 + 1];
                    const float c0 = __cosf(va + rxe);
                    const float c1 = __cosf(vb + rxo);
                    const float d  = c0 * c1;
                    float s = d;
                    float u = __shfl_up_sync(0xffffffffu, s, 1, 4); if (tg >= 1) s *= u;
                    u = __shfl_up_sync(0xffffffffu, s, 2, 4);       if (tg >= 2) s *= u;
                    const float excl = __shfl_up_sync(0xffffffffu, s, 1, 4);
                    const float d1v = __shfl_sync(0xffffffffu, d, 1, 4);
                    const float d2v = __shfl_sync(0xffffffffu, d, 2, 4);
                    const float d3v = __shfl_sync(0xffffffffu, d, 3, 4);
                    float pe, po;
                    if (tg == 0) {
                        pe = c1 * d1v * d2v * d3v;  // wire0: c1*(c2c3)(c4c5)(c6c7)
                        po = d;                      // wire1: c0*c1
                    } else {
                        pe = excl * c0;              // wire 2tg
                        po = s;                      // wire 2tg+1
                    }
                    const int m = bm0 + wm + mt * 16 + gp + h2 * 8;
                    __half2 H;
                    H.x = __float2half_rn(pe);
                    H.y = __float2half_rn(po);
                    *reinterpret_cast<__half2*>(Qh + (size_t)m * E_DIM + n) = H;
                }
            }
        }
    }
}

extern "C" void kernel_launch(void* const* d_in, const int* in_sizes, int n_in,
                              void* d_out, int out_size)
{
    const float* x  = (const float*)d_in[0];
    // d_in[1]=wq, d_in[2]=wk unused: S==1 -> softmax==1 -> attention out == v
    const float* wv = (const float*)d_in[3];
    const float* wc = (const float*)d_in[4];
    const float* bc = (const float*)d_in[5];
    const float* rx = (const float*)d_in[6];
    float* out = (float*)d_out;

    __half *xh, *wvh, *qh, *wch;
    cudaGetSymbolAddress((void**)&xh,  g_xh);
    cudaGetSymbolAddress((void**)&wvh, g_wvh);
    cudaGetSymbolAddress((void**)&qh,  g_qh);
    cudaGetSymbolAddress((void**)&wch, g_wch);

    cudaFuncSetAttribute((const void*)gemm_k<true>,
                         cudaFuncAttributeMaxDynamicSharedMemorySize, SMEM_TOTAL);
    cudaFuncSetAttribute((const void*)gemm_k<false>,
                         cudaFuncAttributeMaxDynamicSharedMemorySize, SMEM_TOTAL);

    // merged prologue: all fp32 -> fp16 conversions
    conv_all<<<CONV_T / 256, 256>>>(x, xh, wv, wvh, wc, wch);

    dim3 grid(E_DIM / BN, M_DIM / BM);   // 8 x 16 = 128 CTAs
    // GEMM1: v = x @ wv^T (fp16), fused quantum epilogue -> q fp16
    gemm_k<true><<<grid, 128, SMEM_TOTAL>>>(xh, wvh, nullptr, nullptr, qh, rx);
    // GEMM2: out = q @ wc^T + bc (fp16)
    gemm_k<false><<<grid, 128, SMEM_TOTAL>>>(qh, wch, bc, out, nullptr, nullptr);
}

// round 16
// speedup vs baseline: 1.2471x; 1.2471x over previous
#include <cuda_runtime.h>
#include <cuda_fp16.h>
#include <math.h>
#include <stdint.h>

// Fixed problem shape: B=2048, S=1, E=1024, H=128, DK=NW=8.
#define M_DIM 2048
#define E_DIM 1024

#define BM 128
#define BN 128
#define BK 32
#define NKIT (E_DIM / BK)      // 32
#define STAGES 3
#define STAGE_BYTES 16384      // A(8K) B(8K)
#define SMEM_TOTAL (STAGES * STAGE_BYTES)   // 49152

// -------- device scratch (no cudaMalloc allowed) --------
__device__ __half g_xh[M_DIM * E_DIM];    // x fp16
__device__ __half g_wvh[E_DIM * E_DIM];   // wv fp16
__device__ __half g_qh[M_DIM * E_DIM];    // q fp16
__device__ __half g_wch[E_DIM * E_DIM];   // wc fp16

// -------- helpers --------
struct alignas(16) hf8 { __half h[8]; };

#define CP_ASYNC16(dst, src) \
    asm volatile("cp.async.cg.shared.global [%0], [%1], 16;\n" :: "r"(dst), "l"(src))

#define LDSM4(r, addr) \
    asm volatile("ldmatrix.sync.aligned.m8n8.x4.shared.b16 {%0,%1,%2,%3}, [%4];" \
        : "=r"((r)[0]), "=r"((r)[1]), "=r"((r)[2]), "=r"((r)[3]) : "r"(addr))

__device__ __forceinline__ void mma_f16(float* d, const uint32_t* a, const uint32_t* b) {
    asm volatile(
        "mma.sync.aligned.m16n8k16.row.col.f32.f16.f16.f32 "
        "{%0,%1,%2,%3}, {%4,%5,%6,%7}, {%8,%9}, {%0,%1,%2,%3};\n"
        : "+f"(d[0]), "+f"(d[1]), "+f"(d[2]), "+f"(d[3])
        : "r"(a[0]), "r"(a[1]), "r"(a[2]), "r"(a[3]), "r"(b[0]), "r"(b[1]));
}

__device__ __forceinline__ hf8 cvt8(float4 a, float4 b) {
    hf8 o;
    o.h[0] = __float2half_rn(a.x); o.h[1] = __float2half_rn(a.y);
    o.h[2] = __float2half_rn(a.z); o.h[3] = __float2half_rn(a.w);
    o.h[4] = __float2half_rn(b.x); o.h[5] = __float2half_rn(b.y);
    o.h[6] = __float2half_rn(b.z); o.h[7] = __float2half_rn(b.w);
    return o;
}

// -------- merged prologue: convert x, wv, wc to fp16 --------
// 8-element tasks: x has 262144, wv 131072, wc 131072. 131072 threads;
// thread t does x-tasks {t, t+131072}, wv-task t, wc-task t.
// Per task: 2x LDG.128 -> cvt -> 1x STG.128. 8 loads in flight per thread.
#define CONV_T (E_DIM * E_DIM / 8)     // 131072 threads = 512 blocks x 256

__global__ void conv_all(const float* __restrict__ x,  __half* __restrict__ xh,
                         const float* __restrict__ wv, __half* __restrict__ wvh,
                         const float* __restrict__ wc, __half* __restrict__ wch)
{
    const int t = blockIdx.x * blockDim.x + threadIdx.x;
    const float4* xs  = reinterpret_cast<const float4*>(x);
    const float4* wvs = reinterpret_cast<const float4*>(wv);
    const float4* wcs = reinterpret_cast<const float4*>(wc);

    // issue all 8 independent 16B loads
    float4 v0 = xs[2 * t];
    float4 v1 = xs[2 * t + 1];
    float4 v2 = xs[2 * (t + CONV_T)];
    float4 v3 = xs[2 * (t + CONV_T) + 1];
    float4 v4 = wvs[2 * t];
    float4 v5 = wvs[2 * t + 1];
    float4 v6 = wcs[2 * t];
    float4 v7 = wcs[2 * t + 1];

    reinterpret_cast<hf8*>(xh)[t]           = cvt8(v0, v1);
    reinterpret_cast<hf8*>(xh)[t + CONV_T]  = cvt8(v2, v3);
    reinterpret_cast<hf8*>(wvh)[t]          = cvt8(v4, v5);
    reinterpret_cast<hf8*>(wch)[t]          = cvt8(v6, v7);
}

// -------- GEMM: C[M,N] = A[M,K] @ B[N,K]^T, single-term fp16 --------
// 256 threads, 8 warps (2x4), warp tile 64x32, 3-stage cp.async pipeline,
// one __syncthreads per K-iter.
// FUSE_Q: epilogue applies closed-form quantum layer -> fp16 Qh
template <bool FUSE_Q>
__global__ void __launch_bounds__(256, 1)
gemm_k(const __half* __restrict__ Ah, const __half* __restrict__ Bh,
       const float* __restrict__ bias, float* __restrict__ C,
       __half* __restrict__ Qh, const float* __restrict__ rx)
{
    extern __shared__ char smem[];
    const uint32_t sbase = (uint32_t)__cvta_generic_to_shared(smem);

    const int tid  = threadIdx.x;
    const int lane = tid & 31;
    const int warp = tid >> 5;
    const int bm0 = blockIdx.y * BM;
    const int bn0 = blockIdx.x * BN;
    const int wm = (warp & 1) * 64;    // 2 warps along M, warp tile 64
    const int wn = (warp >> 1) * 32;   // 4 warps along N, warp tile 32
    const int gp = lane >> 2, tg = lane & 3;

    // ---- preload per-thread epilogue constants (hides tail latency) ----
    float bias_r[8];
    float rxe = 0.0f, rxo = 0.0f;
    if (FUSE_Q) {
        rxe = rx[tg * 2];
        rxo = rx[tg * 2 + 1];
    } else {
#pragma unroll
        for (int nt = 0; nt < 4; nt++) {
            const int n = bn0 + wn + nt * 8 + tg * 2;
            bias_r[2 * nt]     = bias[n];
            bias_r[2 * nt + 1] = bias[n + 1];
        }
    }

    // ---- cp.async per-thread offsets (rows 0..63, second pass +64) ----
    const int r0 = tid >> 2;           // 0..63
    const int c  = tid & 3;            // 16B chunk
    const uint32_t sd0 = (uint32_t)r0 * 64 + (uint32_t)((c ^ ((r0 >> 1) & 3)) * 16);
    const size_t gA0 = (size_t)(bm0 + r0) * E_DIM + c * 8;
    const size_t gB0 = (size_t)(bn0 + r0) * E_DIM + c * 8;

    auto load_stage = [&](int s, int kt) {
        uint32_t base = sbase + (uint32_t)s * STAGE_BYTES;
        CP_ASYNC16(base + sd0,               Ah + gA0 + kt);
        CP_ASYNC16(base + sd0 + 4096,        Ah + gA0 + 64 * E_DIM + kt);
        CP_ASYNC16(base + 8192 + sd0,        Bh + gB0 + kt);
        CP_ASYNC16(base + 8192 + sd0 + 4096, Bh + gB0 + 64 * E_DIM + kt);
        asm volatile("cp.async.commit_group;\n");
    };

    // ---- ldmatrix per-thread addresses (stage 0, ks 0) ----
    const int arow = ((lane >> 3) & 1) * 8 + (lane & 7);
    const int achk = (lane >> 4) & 1;
    uint32_t addrA[4];   // [mt]
#pragma unroll
    for (int mt = 0; mt < 4; mt++) {
        int rA = wm + mt * 16 + arow;
        addrA[mt] = sbase + (uint32_t)rA * 64 +
                    (uint32_t)((achk ^ ((rA >> 1) & 3)) * 16);
    }
    const int brow = ((lane >> 4) & 1) * 8 + (lane & 7);
    const int bchk = (lane >> 3) & 1;
    uint32_t addrB[2];   // [pair]
#pragma unroll
    for (int p = 0; p < 2; p++) {
        int rB = wn + p * 16 + brow;
        addrB[p] = sbase + 8192u + (uint32_t)rB * 64 +
                   (uint32_t)((bchk ^ ((rB >> 1) & 3)) * 16);
    }

    float acc[4][4][4];
#pragma unroll
    for (int mt = 0; mt < 4; mt++)
#pragma unroll
        for (int nt = 0; nt < 4; nt++)
#pragma unroll
            for (int i = 0; i < 4; i++) acc[mt][nt][i] = 0.0f;

    load_stage(0, 0);
    load_stage(1, BK);

    for (int it = 0; it < NKIT; it++) {
        if (it < NKIT - 1) asm volatile("cp.async.wait_group 1;\n");
        else               asm volatile("cp.async.wait_group 0;\n");
        __syncthreads();   // single barrier: all warps done with stage (it-1)%3
        if (it + 2 < NKIT) load_stage((it + 2) % STAGES, (it + 2) * BK);

        const uint32_t so = (uint32_t)(it % STAGES) * STAGE_BYTES;
#pragma unroll
        for (int ks = 0; ks < 2; ks++) {
            const uint32_t kx = (uint32_t)ks << 5;
            uint32_t a[4][4], b[2][4];
#pragma unroll
            for (int mt = 0; mt < 4; mt++)
                LDSM4(a[mt], (addrA[mt] + so) ^ kx);
#pragma unroll
            for (int p = 0; p < 2; p++)
                LDSM4(b[p], (addrB[p] + so) ^ kx);
#pragma unroll
            for (int mt = 0; mt < 4; mt++)
#pragma unroll
                for (int p = 0; p < 2; p++) {
                    mma_f16(acc[mt][2 * p],     a[mt], &b[p][0]);
                    mma_f16(acc[mt][2 * p + 1], a[mt], &b[p][2]);
                }
        }
    }

    // ---- epilogue ----
    if (!FUSE_Q) {
#pragma unroll
        for (int nt = 0; nt < 4; nt++) {
            const int n = bn0 + wn + nt * 8 + tg * 2;
            const float b0 = bias_r[2 * nt], b1 = bias_r[2 * nt + 1];
#pragma unroll
            for (int mt = 0; mt < 4; mt++) {
                const int m = bm0 + wm + mt * 16 + gp;
                float2 o0 = make_float2(acc[mt][nt][0] + b0, acc[mt][nt][1] + b1);
                float2 o1 = make_float2(acc[mt][nt][2] + b0, acc[mt][nt][3] + b1);
                *reinterpret_cast<float2*>(C + (size_t)m * E_DIM + n) = o0;
                *reinterpret_cast<float2*>(C + (size_t)(m + 8) * E_DIM + n) = o1;
            }
        }
    } else {
        // Quantum closed form across each quad (lanes tg=0..3 share one 8-wire
        // head; thread tg owns wires 2tg, 2tg+1). Emit fp16.
        //   c_j = cos(v_j + rx_j);  q[w] = c0..cw (w>=1);  q[0] = c1..c7
#pragma unroll
        for (int nt = 0; nt < 4; nt++) {
            const int n = bn0 + wn + nt * 8 + tg * 2;
#pragma unroll
            for (int mt = 0; mt < 4; mt++) {
#pragma unroll
                for (int h2 = 0; h2 < 2; h2++) {
                    const float va = acc[mt][nt][2 * h2];
                    const float vb = acc[mt][nt][2 * h2 + 1];
                    const float c0 = __cosf(va + rxe);
                    const float c1 = __cosf(vb + rxo);
                    const float d  = c0 * c1;
                    float s = d;
                    float u = __shfl_up_sync(0xffffffffu, s, 1, 4); if (tg >= 1) s *= u;
                    u = __shfl_up_sync(0xffffffffu, s, 2, 4);       if (tg >= 2) s *= u;
                    const float excl = __shfl_up_sync(0xffffffffu, s, 1, 4);
                    const float d1v = __shfl_sync(0xffffffffu, d, 1, 4);
                    const float d2v = __shfl_sync(0xffffffffu, d, 2, 4);
                    const float d3v = __shfl_sync(0xffffffffu, d, 3, 4);
                    float pe, po;
                    if (tg == 0) {
                        pe = c1 * d1v * d2v * d3v;  // wire0: c1*(c2c3)(c4c5)(c6c7)
                        po = d;                      // wire1: c0*c1
                    } else {
                        pe = excl * c0;              // wire 2tg
                        po = s;                      // wire 2tg+1
                    }
                    const int m = bm0 + wm + mt * 16 + gp + h2 * 8;
                    __half2 H;
                    H.x = __float2half_rn(pe);
                    H.y = __float2half_rn(po);
                    *reinterpret_cast<__half2*>(Qh + (size_t)m * E_DIM + n) = H;
                }
            }
        }
    }
}

extern "C" void kernel_launch(void* const* d_in, const int* in_sizes, int n_in,
                              void* d_out, int out_size)
{
    const float* x  = (const float*)d_in[0];
    // d_in[1]=wq, d_in[2]=wk unused: S==1 -> softmax==1 -> attention out == v
    const float* wv = (const float*)d_in[3];
    const float* wc = (const float*)d_in[4];
    const float* bc = (const float*)d_in[5];
    const float* rx = (const float*)d_in[6];
    float* out = (float*)d_out;

    __half *xh, *wvh, *qh, *wch;
    cudaGetSymbolAddress((void**)&xh,  g_xh);
    cudaGetSymbolAddress((void**)&wvh, g_wvh);
    cudaGetSymbolAddress((void**)&qh,  g_qh);
    cudaGetSymbolAddress((void**)&wch, g_wch);

    cudaFuncSetAttribute((const void*)gemm_k<true>,
                         cudaFuncAttributeMaxDynamicSharedMemorySize, SMEM_TOTAL);
    cudaFuncSetAttribute((const void*)gemm_k<false>,
                         cudaFuncAttributeMaxDynamicSharedMemorySize, SMEM_TOTAL);

    // merged prologue: all fp32 -> fp16 conversions, 16B stores, 8 loads in flight
    conv_all<<<CONV_T / 256, 256>>>(x, xh, wv, wvh, wc, wch);

    dim3 grid(E_DIM / BN, M_DIM / BM);   // 8 x 16 = 128 CTAs
    // GEMM1: v = x @ wv^T (fp16), fused quantum epilogue -> q fp16
    gemm_k<true><<<grid, 256, SMEM_TOTAL>>>(xh, wvh, nullptr, nullptr, qh, rx);
    // GEMM2: out = q @ wc^T + bc (fp16)
    gemm_k<false><<<grid, 256, SMEM_TOTAL>>>(qh, wch, bc, out, nullptr, nullptr);
}

// round 17
// speedup vs baseline: 1.2578x; 1.0086x over previous
#include <cuda_runtime.h>
#include <cuda_fp16.h>
#include <math.h>
#include <stdint.h>

// Fixed problem shape: B=2048, S=1, E=1024, H=128, DK=NW=8.
#define M_DIM 2048
#define E_DIM 1024

#define BM 128
#define BN 128
#define BK 32
#define NKIT (E_DIM / BK)      // 32
#define STAGES 3
#define STAGE_BYTES 16384      // A(8K) B(8K)
#define SMEM_TOTAL (STAGES * STAGE_BYTES)   // 49152

// -------- device scratch (no cudaMalloc allowed) --------
__device__ __half g_xh[M_DIM * E_DIM];    // x fp16
__device__ __half g_wvh[E_DIM * E_DIM];   // wv fp16
__device__ __half g_qh[M_DIM * E_DIM];    // q fp16
__device__ __half g_wch[E_DIM * E_DIM];   // wc fp16

// -------- helpers --------
struct alignas(16) hf8 { __half h[8]; };

#define CP_ASYNC16(dst, src) \
    asm volatile("cp.async.cg.shared.global [%0], [%1], 16;\n" :: "r"(dst), "l"(src))

#define LDSM4(r, addr) \
    asm volatile("ldmatrix.sync.aligned.m8n8.x4.shared.b16 {%0,%1,%2,%3}, [%4];" \
        : "=r"((r)[0]), "=r"((r)[1]), "=r"((r)[2]), "=r"((r)[3]) : "r"(addr))

__device__ __forceinline__ void mma_f16(float* d, const uint32_t* a, const uint32_t* b) {
    asm volatile(
        "mma.sync.aligned.m16n8k16.row.col.f32.f16.f16.f32 "
        "{%0,%1,%2,%3}, {%4,%5,%6,%7}, {%8,%9}, {%0,%1,%2,%3};\n"
        : "+f"(d[0]), "+f"(d[1]), "+f"(d[2]), "+f"(d[3])
        : "r"(a[0]), "r"(a[1]), "r"(a[2]), "r"(a[3]), "r"(b[0]), "r"(b[1]));
}

__device__ __forceinline__ hf8 cvt8(float4 a, float4 b) {
    hf8 o;
    o.h[0] = __float2half_rn(a.x); o.h[1] = __float2half_rn(a.y);
    o.h[2] = __float2half_rn(a.z); o.h[3] = __float2half_rn(a.w);
    o.h[4] = __float2half_rn(b.x); o.h[5] = __float2half_rn(b.y);
    o.h[6] = __float2half_rn(b.z); o.h[7] = __float2half_rn(b.w);
    return o;
}

// -------- merged prologue: convert x, wv, wc to fp16 --------
// 8-element tasks: x has 262144, wv 131072, wc 131072. 131072 threads;
// thread t does x-tasks {t, t+131072}, wv-task t, wc-task t.
// Per task: 2x LDG.128 -> cvt -> 1x STG.128. 8 loads in flight per thread.
#define CONV_T (E_DIM * E_DIM / 8)     // 131072 threads = 512 blocks x 256

__global__ void conv_all(const float* __restrict__ x,  __half* __restrict__ xh,
                         const float* __restrict__ wv, __half* __restrict__ wvh,
                         const float* __restrict__ wc, __half* __restrict__ wch)
{
    const int t = blockIdx.x * blockDim.x + threadIdx.x;
    const float4* xs  = reinterpret_cast<const float4*>(x);
    const float4* wvs = reinterpret_cast<const float4*>(wv);
    const float4* wcs = reinterpret_cast<const float4*>(wc);

    // issue all 8 independent 16B loads
    float4 v0 = xs[2 * t];
    float4 v1 = xs[2 * t + 1];
    float4 v2 = xs[2 * (t + CONV_T)];
    float4 v3 = xs[2 * (t + CONV_T) + 1];
    float4 v4 = wvs[2 * t];
    float4 v5 = wvs[2 * t + 1];
    float4 v6 = wcs[2 * t];
    float4 v7 = wcs[2 * t + 1];

    reinterpret_cast<hf8*>(xh)[t]           = cvt8(v0, v1);
    reinterpret_cast<hf8*>(xh)[t + CONV_T]  = cvt8(v2, v3);
    reinterpret_cast<hf8*>(wvh)[t]          = cvt8(v4, v5);
    reinterpret_cast<hf8*>(wch)[t]          = cvt8(v6, v7);
}

// -------- GEMM: C[M,N] = A[M,K] @ B[N,K]^T, single-term fp16 --------
// 256 threads, 8 warps (2x4), warp tile 64x32, 3-stage cp.async pipeline,
// one __syncthreads per K-iter.
// FUSE_Q: epilogue applies closed-form quantum layer -> fp16 Qh
template <bool FUSE_Q>
__global__ void __launch_bounds__(256, 1)
gemm_k(const __half* __restrict__ Ah, const __half* __restrict__ Bh,
       const float* __restrict__ bias, float* __restrict__ C,
       __half* __restrict__ Qh, const float* __restrict__ rx)
{
    extern __shared__ char smem[];
    const uint32_t sbase = (uint32_t)__cvta_generic_to_shared(smem);

    const int tid  = threadIdx.x;
    const int lane = tid & 31;
    const int warp = tid >> 5;
    const int bm0 = blockIdx.y * BM;
    const int bn0 = blockIdx.x * BN;
    const int wm = (warp & 1) * 64;    // 2 warps along M, warp tile 64
    const int wn = (warp >> 1) * 32;   // 4 warps along N, warp tile 32
    const int gp = lane >> 2, tg = lane & 3;

    // ---- preload per-thread epilogue constants (hides tail latency) ----
    float bias_r[8];
    float rxe = 0.0f, rxo = 0.0f;
    if (FUSE_Q) {
        rxe = rx[tg * 2];
        rxo = rx[tg * 2 + 1];
    } else {
#pragma unroll
        for (int nt = 0; nt < 4; nt++) {
            const int n = bn0 + wn + nt * 8 + tg * 2;
            bias_r[2 * nt]     = bias[n];
            bias_r[2 * nt + 1] = bias[n + 1];
        }
    }

    // ---- cp.async per-thread offsets (rows 0..63, second pass +64) ----
    const int r0 = tid >> 2;           // 0..63
    const int c  = tid & 3;            // 16B chunk
    const uint32_t sd0 = (uint32_t)r0 * 64 + (uint32_t)((c ^ ((r0 >> 1) & 3)) * 16);
    const size_t gA0 = (size_t)(bm0 + r0) * E_DIM + c * 8;
    const size_t gB0 = (size_t)(bn0 + r0) * E_DIM + c * 8;

    auto load_stage = [&](int s, int kt) {
        uint32_t base = sbase + (uint32_t)s * STAGE_BYTES;
        CP_ASYNC16(base + sd0,               Ah + gA0 + kt);
        CP_ASYNC16(base + sd0 + 4096,        Ah + gA0 + 64 * E_DIM + kt);
        CP_ASYNC16(base + 8192 + sd0,        Bh + gB0 + kt);
        CP_ASYNC16(base + 8192 + sd0 + 4096, Bh + gB0 + 64 * E_DIM + kt);
        asm volatile("cp.async.commit_group;\n");
    };

    // ---- ldmatrix per-thread addresses (stage 0, ks 0) ----
    const int arow = ((lane >> 3) & 1) * 8 + (lane & 7);
    const int achk = (lane >> 4) & 1;
    uint32_t addrA[4];   // [mt]
#pragma unroll
    for (int mt = 0; mt < 4; mt++) {
        int rA = wm + mt * 16 + arow;
        addrA[mt] = sbase + (uint32_t)rA * 64 +
                    (uint32_t)((achk ^ ((rA >> 1) & 3)) * 16);
    }
    const int brow = ((lane >> 4) & 1) * 8 + (lane & 7);
    const int bchk = (lane >> 3) & 1;
    uint32_t addrB[2];   // [pair]
#pragma unroll
    for (int p = 0; p < 2; p++) {
        int rB = wn + p * 16 + brow;
        addrB[p] = sbase + 8192u + (uint32_t)rB * 64 +
                   (uint32_t)((bchk ^ ((rB >> 1) & 3)) * 16);
    }

    float acc[4][4][4];
#pragma unroll
    for (int mt = 0; mt < 4; mt++)
#pragma unroll
        for (int nt = 0; nt < 4; nt++)
#pragma unroll
            for (int i = 0; i < 4; i++) acc[mt][nt][i] = 0.0f;

    load_stage(0, 0);
    load_stage(1, BK);

    for (int it = 0; it < NKIT; it++) {
        if (it < NKIT - 1) asm volatile("cp.async.wait_group 1;\n");
        else               asm volatile("cp.async.wait_group 0;\n");
        __syncthreads();   // single barrier: all warps done with stage (it-1)%3
        if (it + 2 < NKIT) load_stage((it + 2) % STAGES, (it + 2) * BK);

        const uint32_t so = (uint32_t)(it % STAGES) * STAGE_BYTES;
#pragma unroll
        for (int ks = 0; ks < 2; ks++) {
            const uint32_t kx = (uint32_t)ks << 5;
            uint32_t a[4][4], b[2][4];
#pragma unroll
            for (int mt = 0; mt < 4; mt++)
                LDSM4(a[mt], (addrA[mt] + so) ^ kx);
#pragma unroll
            for (int p = 0; p < 2; p++)
                LDSM4(b[p], (addrB[p] + so) ^ kx);
#pragma unroll
            for (int mt = 0; mt < 4; mt++)
#pragma unroll
                for (int p = 0; p < 2; p++) {
                    mma_f16(acc[mt][2 * p],     a[mt], &b[p][0]);
                    mma_f16(acc[mt][2 * p + 1], a[mt], &b[p][2]);
                }
        }
    }

    // ---- epilogue ----
    if (!FUSE_Q) {
#pragma unroll
        for (int nt = 0; nt < 4; nt++) {
            const int n = bn0 + wn + nt * 8 + tg * 2;
            const float b0 = bias_r[2 * nt], b1 = bias_r[2 * nt + 1];
#pragma unroll
            for (int mt = 0; mt < 4; mt++) {
                const int m = bm0 + wm + mt * 16 + gp;
                float2 o0 = make_float2(acc[mt][nt][0] + b0, acc[mt][nt][1] + b1);
                float2 o1 = make_float2(acc[mt][nt][2] + b0, acc[mt][nt][3] + b1);
                *reinterpret_cast<float2*>(C + (size_t)m * E_DIM + n) = o0;
                *reinterpret_cast<float2*>(C + (size_t)(m + 8) * E_DIM + n) = o1;
            }
        }
    } else {
        // Quantum closed form across each quad (lanes tg=0..3 share one 8-wire
        // head; thread tg owns wires 2tg, 2tg+1). Emit fp16.
        //   c_j = cos(v_j + rx_j);  q[w] = c0..cw (w>=1);  q[0] = c1..c7
#pragma unroll
        for (int nt = 0; nt < 4; nt++) {
            const int n = bn0 + wn + nt * 8 + tg * 2;
#pragma unroll
            for (int mt = 0; mt < 4; mt++) {
#pragma unroll
                for (int h2 = 0; h2 < 2; h2++) {
                    const float va = acc[mt][nt][2 * h2];
                    const float vb = acc[mt][nt][2 * h2 + 1];
                    const float c0 = __cosf(va + rxe);
                    const float c1 = __cosf(vb + rxo);
                    const float d  = c0 * c1;
                    float s = d;
                    float u = __shfl_up_sync(0xffffffffu, s, 1, 4); if (tg >= 1) s *= u;
                    u = __shfl_up_sync(0xffffffffu, s, 2, 4);       if (tg >= 2) s *= u;
                    const float excl = __shfl_up_sync(0xffffffffu, s, 1, 4);
                    const float d1v = __shfl_sync(0xffffffffu, d, 1, 4);
                    const float d2v = __shfl_sync(0xffffffffu, d, 2, 4);
                    const float d3v = __shfl_sync(0xffffffffu, d, 3, 4);
                    float pe, po;
                    if (tg == 0) {
                        pe = c1 * d1v * d2v * d3v;  // wire0: c1*(c2c3)(c4c5)(c6c7)
                        po = d;                      // wire1: c0*c1
                    } else {
                        pe = excl * c0;              // wire 2tg
                        po = s;                      // wire 2tg+1
                    }
                    const int m = bm0 + wm + mt * 16 + gp + h2 * 8;
                    __half2 H;
                    H.x = __float2half_rn(pe);
                    H.y = __float2half_rn(po);
                    *reinterpret_cast<__half2*>(Qh + (size_t)m * E_DIM + n) = H;
                }
            }
        }
    }
}

extern "C" void kernel_launch(void* const* d_in, const int* in_sizes, int n_in,
                              void* d_out, int out_size)
{
    const float* x  = (const float*)d_in[0];
    // d_in[1]=wq, d_in[2]=wk unused: S==1 -> softmax==1 -> attention out == v
    const float* wv = (const float*)d_in[3];
    const float* wc = (const float*)d_in[4];
    const float* bc = (const float*)d_in[5];
    const float* rx = (const float*)d_in[6];
    float* out = (float*)d_out;

    __half *xh, *wvh, *qh, *wch;
    cudaGetSymbolAddress((void**)&xh,  g_xh);
    cudaGetSymbolAddress((void**)&wvh, g_wvh);
    cudaGetSymbolAddress((void**)&qh,  g_qh);
    cudaGetSymbolAddress((void**)&wch, g_wch);

    cudaFuncSetAttribute((const void*)gemm_k<true>,
                         cudaFuncAttributeMaxDynamicSharedMemorySize, SMEM_TOTAL);
    cudaFuncSetAttribute((const void*)gemm_k<false>,
                         cudaFuncAttributeMaxDynamicSharedMemorySize, SMEM_TOTAL);

    // merged prologue: all fp32 -> fp16 conversions, 16B stores, 8 loads in flight
    conv_all<<<CONV_T / 256, 256>>>(x, xh, wv, wvh, wc, wch);

    dim3 grid(E_DIM / BN, M_DIM / BM);   // 8 x 16 = 128 CTAs
    // GEMM1: v = x @ wv^T (fp16), fused quantum epilogue -> q fp16
    gemm_k<true><<<grid, 256, SMEM_TOTAL>>>(xh, wvh, nullptr, nullptr, qh, rx);
    // GEMM2: out = q @ wc^T + bc (fp16)
    gemm_k<false><<<grid, 256, SMEM_TOTAL>>>(qh, wch, bc, out, nullptr, nullptr);
}